// round 1
// baseline (speedup 1.0000x reference)
#include <cuda_runtime.h>
#include <cuda_bf16.h>

// InternalCoordinateTransform: x:(2048,7500) f32, z_mat:(2497,4) i32,
// 6 param vectors of len 2497. Out = x with slots [3*a4 .. 3*a4+2] replaced
// by normalized (bond, angle, dihedral) per z-matrix row.

#define NDIM   7500
#define NF4    1875          // NDIM/4
#define ZROWS  2497
#define PI_F   3.14159265358979f
#define TWO_PI 6.28318530717959f

__device__ __forceinline__ float rsqrt_ap(float x) {
    float r; asm("rsqrt.approx.f32 %0, %1;" : "=f"(r) : "f"(x)); return r;
}
__device__ __forceinline__ float sqrt_ap(float x) {
    float r; asm("sqrt.approx.f32 %0, %1;" : "=f"(r) : "f"(x)); return r;
}
__device__ __forceinline__ float rcp_ap(float x) {
    float r; asm("rcp.approx.f32 %0, %1;" : "=f"(r) : "f"(x)); return r;
}

// Hastings-style acos, |err| ~ 1e-7 rad. x must be in [-1, 1].
__device__ __forceinline__ float acos_fast(float x) {
    float xa = fabsf(x);
    float p = -0.0012624911f;
    p = fmaf(p, xa,  0.0066700901f);
    p = fmaf(p, xa, -0.0170881256f);
    p = fmaf(p, xa,  0.0308918810f);
    p = fmaf(p, xa, -0.0501743046f);
    p = fmaf(p, xa,  0.0889789874f);
    p = fmaf(p, xa, -0.2145988016f);
    p = fmaf(p, xa,  1.5707963050f);
    float r = sqrt_ap(1.0f - xa) * p;
    return (x >= 0.0f) ? r : (PI_F - r);
}

// Full-quadrant atan2, degree-11 minimax core on [0,1], |err| ~ few e-6 rad.
__device__ __forceinline__ float atan2_fast(float y, float x) {
    float ax = fabsf(x), ay = fabsf(y);
    float mx = fmaxf(fmaxf(ax, ay), 1e-35f);
    float mn = fminf(ax, ay);
    float t  = mn * rcp_ap(mx);
    float s  = t * t;
    float p = -0.01172120f;
    p = fmaf(p, s,  0.05265332f);
    p = fmaf(p, s, -0.11643287f);
    p = fmaf(p, s,  0.19354346f);
    p = fmaf(p, s, -0.33262347f);
    p = fmaf(p, s,  0.99997726f);
    float r = t * p;
    if (ay > ax)   r = 1.57079632679f - r;
    if (x < 0.0f)  r = PI_F - r;
    return copysignf(r, y);
}

__global__ __launch_bounds__(256)
void ict_kernel(const float* __restrict__ x,
                const int4*  __restrict__ zmat,
                const float* __restrict__ mb, const float* __restrict__ sb,
                const float* __restrict__ ma, const float* __restrict__ sa,
                const float* __restrict__ md, const float* __restrict__ sd,
                float* __restrict__ out, int zrows)
{
    __shared__ float row[NDIM];
    const int b   = blockIdx.x;
    const int tid = threadIdx.x;
    const size_t base = (size_t)b * NDIM;

    // Stage full row into SMEM, coalesced float4.
    const float4* __restrict__ xin = (const float4*)(x + base);
    float4* rf4 = (float4*)row;
#pragma unroll
    for (int k = 0; k < 8; k++) {
        int idx = tid + k * 256;
        if (idx < NF4) rf4[idx] = xin[idx];
    }
    __syncthreads();

    // First 9 output floats (atoms 0,1,2) are a straight copy.
    if (tid < 9) out[base + tid] = row[tid];

    for (int i = tid; i < zrows; i += 256) {
        int4 zm = zmat[i];            // (a4, a1, a2, a3)
        const float* P1 = row + 3 * zm.y;
        const float* P2 = row + 3 * zm.z;
        const float* P3 = row + 3 * zm.w;
        const float* P4 = row + 3 * zm.x;

        float p1x = P1[0], p1y = P1[1], p1z = P1[2];
        float p2x = P2[0], p2y = P2[1], p2z = P2[2];
        float p3x = P3[0], p3y = P3[1], p3z = P3[2];
        float p4x = P4[0], p4y = P4[1], p4z = P4[2];

        float d21x = p2x - p1x, d21y = p2y - p1y, d21z = p2z - p1z;
        float d41x = p4x - p1x, d41y = p4y - p1y, d41z = p4z - p1z;

        float s21 = fmaf(d21x, d21x, fmaf(d21y, d21y, d21z * d21z));
        float s41 = fmaf(d41x, d41x, fmaf(d41y, d41y, d41z * d41z));
        float r21 = rsqrt_ap(s21);
        float r41 = rsqrt_ap(s41);

        float bond = s41 * r41;       // |p4 - p1|

        // angle between unit(p2-p1) and unit(p4-p1)
        float dotc = fmaf(d21x, d41x, fmaf(d21y, d41y, d21z * d41z));
        float cosang = fminf(fmaxf(dotc * r21 * r41, -1.0f), 1.0f);
        float ang = acos_fast(cosang);

        // dihedral. u = unit(p2-p1) = -b1; projections are sign-invariant,
        // and -atan2(cross(b1,v).w, xx) == atan2(cross(u,v).w, xx).
        float ux = d21x * r21, uy = d21y * r21, uz = d21z * r21;
        float b0x = p3x - p2x, b0y = p3y - p2y, b0z = p3z - p2z;

        float db0 = fmaf(b0x, ux, fmaf(b0y, uy, b0z * uz));
        float vx = fmaf(-db0, ux, b0x);
        float vy = fmaf(-db0, uy, b0y);
        float vz = fmaf(-db0, uz, b0z);

        float db2 = fmaf(d41x, ux, fmaf(d41y, uy, d41z * uz));
        float wx = fmaf(-db2, ux, d41x);
        float wy = fmaf(-db2, uy, d41y);
        float wz = fmaf(-db2, uz, d41z);

        float xx = fmaf(vx, wx, fmaf(vy, wy, vz * wz));
        float cx = fmaf(uy, vz, -uz * vy);
        float cy = fmaf(uz, vx, -ux * vz);
        float cz = fmaf(ux, vy, -uy * vx);
        float yy = fmaf(cx, wx, fmaf(cy, wy, cz * wz));
        float dihe = atan2_fast(yy, xx);

        // normalize
        float ob = (bond - mb[i]) * rcp_ap(sb[i]);
        float oa = (ang  - ma[i]) * rcp_ap(sa[i]);
        float dd = dihe - md[i];
        dd = (dd < -PI_F) ? dd + TWO_PI : dd;
        dd = (dd >  PI_F) ? dd - TWO_PI : dd;
        float od = dd * rcp_ap(sd[i]);

        float* o = out + base + 3 * zm.x;
        o[0] = ob;
        o[1] = oa;
        o[2] = od;
    }
}

extern "C" void kernel_launch(void* const* d_in, const int* in_sizes, int n_in,
                              void* d_out, int out_size)
{
    const float* x  = (const float*)d_in[0];
    const int*   zm = (const int*)  d_in[1];
    const float* mb = (const float*)d_in[2];
    const float* sb = (const float*)d_in[3];
    const float* ma = (const float*)d_in[4];
    const float* sa = (const float*)d_in[5];
    const float* md = (const float*)d_in[6];
    const float* sd = (const float*)d_in[7];

    int bsz   = in_sizes[0] / NDIM;   // 2048
    int zrows = in_sizes[2];          // 2497

    ict_kernel<<<bsz, 256>>>(x, (const int4*)zm, mb, sb, ma, sa, md, sd,
                             (float*)d_out, zrows);
}